// round 17
// baseline (speedup 1.0000x reference)
#include <cuda_runtime.h>
#include <cuda_fp16.h>
#include <cstdint>
#include <math.h>

// ---------------- problem constants ----------------
#define B_SZ     256
#define N_TOK    197
#define D_L      512
#define D_G      768
#define M_FINE   (B_SZ * N_TOK)          // 50432
#define TOPK     5

#define OFF_G    0
#define OFF_LS   (B_SZ * D_G)                         // 196608
#define OFF_FINE (OFF_LS + 1)                         // 196609
#define OFF_TOP  (OFF_FINE + (size_t)M_FINE * D_L)

// ---------------- device scratch (all-fp16 GEMM operands) ----------------
__device__ __align__(16) __half g_A1h[(size_t)M_FINE * D_L];   // fine input (fp16)
__device__ __align__(16) __half g_Hfh[(size_t)M_FINE * D_L];   // fine hidden (fp16, pre-BN)
__device__ __align__(16) __half g_W1h[D_L * D_L];
__device__ __align__(16) __half g_W2h[D_L * D_L];
__device__ __align__(16) __half g_V1h[D_G * D_L];
__device__ __align__(16) __half g_V2h[D_G * D_G];
__device__ __align__(16) __half g_gAh[B_SZ * D_L];             // global input (fp16)
__device__ __align__(16) __half g_Hgh[B_SZ * D_G];             // global hidden (fp16, pre-BN)
__device__ __align__(16) float g_G [B_SZ * D_G];
__device__ __align__(16) float g_sums_f[2 * D_L];
__device__ __align__(16) float g_sums_g[2 * D_G];
__device__ __align__(16) float g_scale_f[D_L], g_shift_f[D_L];
__device__ __align__(16) float g_scale_g[D_G], g_shift_g[D_G];

// ---------------- helpers ----------------
__device__ __forceinline__ uint32_t s2u(const void* p) {
    uint32_t a;
    asm("{ .reg .u64 t; cvta.to.shared.u64 t, %1; cvt.u32.u64 %0, t; }" : "=r"(a) : "l"(p));
    return a;
}
__device__ __forceinline__ void ldsm_x4(uint32_t* r, uint32_t addr) {
    asm volatile("ldmatrix.sync.aligned.m8n8.x4.shared.b16 {%0,%1,%2,%3}, [%4];"
        : "=r"(r[0]), "=r"(r[1]), "=r"(r[2]), "=r"(r[3]) : "r"(addr));
}
__device__ __forceinline__ void mma_f32(float* c, const uint32_t* a, const uint32_t* b) {
    asm volatile("mma.sync.aligned.m16n8k16.row.col.f32.f16.f16.f32 "
        "{%0,%1,%2,%3}, {%4,%5,%6,%7}, {%8,%9}, {%0,%1,%2,%3};"
        : "+f"(c[0]), "+f"(c[1]), "+f"(c[2]), "+f"(c[3])
        : "r"(a[0]), "r"(a[1]), "r"(a[2]), "r"(a[3]), "r"(b[0]), "r"(b[1]));
}
// relu(a*s + t) on a packed half2 register (fp32 math)
__device__ __forceinline__ void bnfix(uint32_t& r, float2 s, float2 t) {
    __half2 h = *(__half2*)&r;
    float2 f = __half22float2(h);
    f.x = fmaxf(fmaf(f.x, s.x, t.x), 0.0f);
    f.y = fmaxf(fmaf(f.y, s.y, t.y), 0.0f);
    __half2 o = __floats2half2_rn(f.x, f.y);
    r = *(uint32_t*)&o;
}

// ---------------- pure-fp16 HMMA GEMM: C = op(A)[M,K] @ B[N,K]^T + bias ----------------
// Both operands fp16 in global, loaded via cp.async (3-stage pipeline).
// If BNRELU: op(A)=relu(A*bnscale[k]+bnshift[k]) applied to A FRAGMENTS post-ldsm
//            (frag k-coords: regs{0,1} at k=(lane&3)*2{,+1}; regs{2,3} at +8).
// CTA 128x128, BK=32, 4 warps (warp tile 64x64).
// smem per stage: A 10240 B | B 10240 B ; stage stride 20480; rows padded to 80 B.
// STATS=true : writes Ch (fp16) + per-column sum/sumsq into sums[0..N),[N..2N).
// STATS=false: writes Cf (fp32).
template<bool STATS, bool BNRELU>
__global__ void __launch_bounds__(128, 2)
hgemm_kernel(const __half* __restrict__ A, const __half* __restrict__ B,
             const float* __restrict__ bias,
             const float* __restrict__ bnscale, const float* __restrict__ bnshift,
             __half* __restrict__ Ch, float* __restrict__ Cf,
             float* __restrict__ sums, int N, int K)
{
    extern __shared__ char sm[];
    const uint32_t sbase = s2u(sm);
    const int tid  = threadIdx.x;
    const int lane = tid & 31, wid = tid >> 5;
    const int wm = wid & 1, wn = wid >> 1;          // 2 x 2 warp grid, warp tile 64x64
    const int m0 = blockIdx.y * 128, n0 = blockIdx.x * 128;
    const int grp = lane >> 3, gr = lane & 7;

    // A frag address (x4 = 16x16 fp16 tile)
    const uint32_t aAddr = sbase + (uint32_t)((wm * 64 + gr + (grp & 1) * 8) * 80 + (grp >> 1) * 16);
    // B frag address: x4 packs TWO adjacent nt fragments
    const uint32_t bAddr = sbase + 10240u
                         + (uint32_t)((wn * 64 + (grp >> 1) * 8 + gr) * 80 + (grp & 1) * 16);

    const int cbn = (lane & 3) << 1;   // fragment k-offset within k16

    float acc[4][8][4];
    #pragma unroll
    for (int i = 0; i < 4; i++)
        #pragma unroll
        for (int j = 0; j < 8; j++)
            #pragma unroll
            for (int q = 0; q < 4; q++) acc[i][j][q] = 0.0f;

    const int NT = K >> 5;

    auto cp_stage = [&](int kc, int st) {
        const uint32_t so = (uint32_t)st * 20480u;
        #pragma unroll
        for (int p = 0; p < 4; p++) {
            int i = tid + 128 * p; int row = i >> 2, sg = i & 3;
            uint32_t da = sbase + so + (uint32_t)(row * 80 + sg * 16);
            const __half* sa = A + (size_t)(m0 + row) * K + kc + sg * 8;
            asm volatile("cp.async.cg.shared.global [%0], [%1], 16;" :: "r"(da), "l"(sa));
            const __half* sb = B + (size_t)(n0 + row) * K + kc + sg * 8;
            asm volatile("cp.async.cg.shared.global [%0], [%1], 16;" :: "r"(da + 10240u), "l"(sb));
        }
        asm volatile("cp.async.commit_group;" ::: "memory");
    };

    cp_stage(0, 0);
    cp_stage(32, 1);

    for (int kt = 0; kt < NT; kt++) {
        if (kt + 1 < NT) { asm volatile("cp.async.wait_group 1;" ::: "memory"); }
        else             { asm volatile("cp.async.wait_group 0;" ::: "memory"); }
        __syncthreads();
        if (kt + 2 < NT) cp_stage((kt + 2) << 5, (kt + 2) % 3);

        const uint32_t so = (uint32_t)(kt % 3) * 20480u;
        #pragma unroll
        for (int k16 = 0; k16 < 2; k16++) {
            const uint32_t kb = so + (uint32_t)(k16 * 32);
            uint32_t aF[4][4];
            #pragma unroll
            for (int mt = 0; mt < 4; mt++)
                ldsm_x4(aF[mt], aAddr + kb + (uint32_t)(mt * 1280));

            if (BNRELU) {
                const int kgl = (kt << 5) + (k16 << 4) + cbn;
                float2 sl = __ldg((const float2*)(bnscale + kgl));
                float2 tl = __ldg((const float2*)(bnshift + kgl));
                float2 sh = __ldg((const float2*)(bnscale + kgl + 8));
                float2 th = __ldg((const float2*)(bnshift + kgl + 8));
                #pragma unroll
                for (int mt = 0; mt < 4; mt++) {
                    bnfix(aF[mt][0], sl, tl);
                    bnfix(aF[mt][1], sl, tl);
                    bnfix(aF[mt][2], sh, th);
                    bnfix(aF[mt][3], sh, th);
                }
            }

            #pragma unroll
            for (int ntp = 0; ntp < 4; ntp++) {
                uint32_t bb[4];
                ldsm_x4(bb, bAddr + kb + (uint32_t)(ntp * 1280));
                const int n0t = 2 * ntp, n1t = 2 * ntp + 1;
                #pragma unroll
                for (int mt = 0; mt < 4; mt++) mma_f32(acc[mt][n0t], aF[mt], bb + 0);
                #pragma unroll
                for (int mt = 0; mt < 4; mt++) mma_f32(acc[mt][n1t], aF[mt], bb + 2);
            }
        }
    }

    // ---- epilogue ----
    float* ssum = (float*)sm;   // [0..127]=col sum, [128..255]=col sumsq
    if (STATS) {
        __syncthreads();
        if (tid < 128) { ssum[tid] = 0.0f; ssum[128 + tid] = 0.0f; }
        __syncthreads();
    }

    const int erow = m0 + wm * 64 + (lane >> 2);
    const int ecol = n0 + wn * 64 + ((lane & 3) << 1);
    #pragma unroll
    for (int nt = 0; nt < 8; nt++) {
        int c = ecol + nt * 8;
        float b0 = __ldg(&bias[c]), b1 = __ldg(&bias[c + 1]);
        float cs0 = 0.f, cq0 = 0.f, cs1 = 0.f, cq1 = 0.f;
        #pragma unroll
        for (int mt = 0; mt < 4; mt++) {
            int r = erow + mt * 16;
            float v0 = acc[mt][nt][0] + b0;
            float v1 = acc[mt][nt][1] + b1;
            float v2 = acc[mt][nt][2] + b0;
            float v3 = acc[mt][nt][3] + b1;
            if (STATS) {
                Ch[(size_t)r * N + c]           = __float2half_rn(v0);
                Ch[(size_t)r * N + c + 1]       = __float2half_rn(v1);
                Ch[(size_t)(r + 8) * N + c]     = __float2half_rn(v2);
                Ch[(size_t)(r + 8) * N + c + 1] = __float2half_rn(v3);
                cs0 += v0 + v2; cq0 = fmaf(v0, v0, fmaf(v2, v2, cq0));
                cs1 += v1 + v3; cq1 = fmaf(v1, v1, fmaf(v3, v3, cq1));
            } else {
                Cf[(size_t)r * N + c]           = v0;
                Cf[(size_t)r * N + c + 1]       = v1;
                Cf[(size_t)(r + 8) * N + c]     = v2;
                Cf[(size_t)(r + 8) * N + c + 1] = v3;
            }
        }
        if (STATS) {
            #pragma unroll
            for (int o = 4; o <= 16; o <<= 1) {
                cs0 += __shfl_xor_sync(0xffffffffu, cs0, o);
                cq0 += __shfl_xor_sync(0xffffffffu, cq0, o);
                cs1 += __shfl_xor_sync(0xffffffffu, cs1, o);
                cq1 += __shfl_xor_sync(0xffffffffu, cq1, o);
            }
            if (lane < 4) {
                int lc = wn * 64 + lane * 2 + nt * 8;
                atomicAdd(&ssum[lc],           cs0);
                atomicAdd(&ssum[128 + lc],     cq0);
                atomicAdd(&ssum[lc + 1],       cs1);
                atomicAdd(&ssum[128 + lc + 1], cq1);
            }
        }
    }
    if (STATS) {
        __syncthreads();
        if (tid < 128) {
            atomicAdd(&sums[n0 + tid],     ssum[tid]);
            atomicAdd(&sums[N + n0 + tid], ssum[128 + tid]);
        }
    }
}

#define GEMM_SMEM 61440

// ---------------- fp32 -> fp16 convert (8 floats / thread) ----------------
__global__ void cvt_kernel(const float* __restrict__ x,
                           __half* __restrict__ o, int n8) {
    int i = blockIdx.x * blockDim.x + threadIdx.x;
    if (i >= n8) return;
    float4 v0 = ((const float4*)x)[2 * (size_t)i];
    float4 v1 = ((const float4*)x)[2 * (size_t)i + 1];
    uint4 out;
    __half2* ov = (__half2*)&out;
    ov[0] = __floats2half2_rn(v0.x, v0.y);
    ov[1] = __floats2half2_rn(v0.z, v0.w);
    ov[2] = __floats2half2_rn(v1.x, v1.y);
    ov[3] = __floats2half2_rn(v1.z, v1.w);
    ((uint4*)o)[i] = out;
}

// ---------------- init: zero BN accumulators ----------------
__global__ void init_kernel() {
    int t = blockIdx.x * blockDim.x + threadIdx.x;
    if (t < 2 * D_L) g_sums_f[t] = 0.0f;
    if (t < 2 * D_G) g_sums_g[t] = 0.0f;
}

template<int C>
__global__ void bn_finalize_kernel(const float* __restrict__ sums,
                                   const float* __restrict__ gamma,
                                   const float* __restrict__ beta,
                                   float invM,
                                   float* __restrict__ scale,
                                   float* __restrict__ shift) {
    int c = threadIdx.x;
    if (c >= C) return;
    float m   = sums[c] * invM;
    float var = sums[C + c] * invM - m * m;
    float inv = rsqrtf(var + 1e-5f);
    float sc  = gamma[c] * inv;
    scale[c] = sc;
    shift[c] = beta[c] - m * sc;
}

// ---------------- L2 normalize + logit_scale ----------------
__global__ void l2norm_kernel(const float* __restrict__ G,
                              const float* __restrict__ ls,
                              float* __restrict__ out) {
    __shared__ float red[256];
    const int r = blockIdx.x, t = threadIdx.x;
    const float* g = G + (size_t)r * D_G;
    float s = 0.0f;
    for (int c = t; c < D_G; c += 256) { float v = g[c]; s = fmaf(v, v, s); }
    red[t] = s; __syncthreads();
    for (int o = 128; o > 0; o >>= 1) {
        if (t < o) red[t] += red[t + o];
        __syncthreads();
    }
    float inv = rsqrtf(red[0]);
    for (int c = t; c < D_G; c += 256)
        out[OFF_G + (size_t)r * D_G + c] = g[c] * inv;
    if (r == 0 && t == 0) out[OFF_LS] = expf(ls[0]);
}

// ---------------- fused fine epilogue: top-k select + gather + token mean ----------------
__global__ void fine_epilogue_kernel(const float* __restrict__ attn,
                                     const float* __restrict__ X2,
                                     float* __restrict__ outTop) {
    __shared__ float sv[256];
    __shared__ int   si[256];
    __shared__ int   sel[TOPK + 1];
    const int b = blockIdx.x, t = threadIdx.x;
    const float NEG = __int_as_float(0xff800000);

    float myv = (t < N_TOK - 1) ? attn[(size_t)b * (N_TOK - 1) + t] : NEG;
    if (t == 0) sel[0] = 0;
    __syncthreads();

    #pragma unroll 1
    for (int k = 0; k < TOPK; k++) {
        if (t < 256) { sv[t] = myv; si[t] = t; }
        __syncthreads();
        for (int o = 128; o > 0; o >>= 1) {
            if (t < o) {
                float v2 = sv[t + o]; int i2 = si[t + o];
                if (v2 > sv[t] || (v2 == sv[t] && i2 < si[t])) { sv[t] = v2; si[t] = i2; }
            }
            __syncthreads();
        }
        int win = si[0];
        if (t == 0)  sel[k + 1] = win + 1;
        if (t == win) myv = NEG;
        __syncthreads();
    }

    const float* xb = X2 + (size_t)b * N_TOK * D_L;
    float* ob = outTop + (size_t)b * (TOPK + 2) * D_L;
    #pragma unroll
    for (int j = 0; j < TOPK + 1; j++)
        ob[(size_t)j * D_L + t] = xb[(size_t)sel[j] * D_L + t];

    float s = 0.0f;
    #pragma unroll 4
    for (int n = 0; n < N_TOK; n++) s += xb[(size_t)n * D_L + t];
    ob[(size_t)(TOPK + 1) * D_L + t] = s * (1.0f / (float)N_TOK);
}

// ---------------- launch ----------------
extern "C" void kernel_launch(void* const* d_in, const int* in_sizes, int n_in,
                              void* d_out, int out_size)
{
    const float* image_features = (const float*)d_in[0];
    const float* fine_feat      = (const float*)d_in[1];
    const float* fine_attn      = (const float*)d_in[2];
    const float* logit_scale    = (const float*)d_in[3];
    const float* vpt_w1  = (const float*)d_in[4];
    const float* vpt_b1  = (const float*)d_in[5];
    const float* vpt_g1  = (const float*)d_in[6];
    const float* vpt_be1 = (const float*)d_in[7];
    const float* vpt_w2  = (const float*)d_in[8];
    const float* vpt_b2  = (const float*)d_in[9];
    const float* mid_w1  = (const float*)d_in[10];
    const float* mid_b1  = (const float*)d_in[11];
    const float* mid_g1  = (const float*)d_in[12];
    const float* mid_be1 = (const float*)d_in[13];
    const float* mid_w2  = (const float*)d_in[14];
    const float* mid_b2  = (const float*)d_in[15];
    float* out = (float*)d_out;

    __half *A1h, *Hfh, *W1h, *W2h, *V1h, *V2h, *gAh, *Hgh;
    float *G, *sf, *sg, *scf, *shf, *scg, *shg;
    cudaGetSymbolAddress((void**)&A1h, g_A1h);
    cudaGetSymbolAddress((void**)&Hfh, g_Hfh);
    cudaGetSymbolAddress((void**)&W1h, g_W1h);
    cudaGetSymbolAddress((void**)&W2h, g_W2h);
    cudaGetSymbolAddress((void**)&V1h, g_V1h);
    cudaGetSymbolAddress((void**)&V2h, g_V2h);
    cudaGetSymbolAddress((void**)&gAh, g_gAh);
    cudaGetSymbolAddress((void**)&Hgh, g_Hgh);
    cudaGetSymbolAddress((void**)&G,   g_G);
    cudaGetSymbolAddress((void**)&sf,  g_sums_f);  cudaGetSymbolAddress((void**)&sg, g_sums_g);
    cudaGetSymbolAddress((void**)&scf, g_scale_f); cudaGetSymbolAddress((void**)&shf, g_shift_f);
    cudaGetSymbolAddress((void**)&scg, g_scale_g); cudaGetSymbolAddress((void**)&shg, g_shift_g);

    cudaFuncSetAttribute(hgemm_kernel<true,  false>, cudaFuncAttributeMaxDynamicSharedMemorySize, GEMM_SMEM);
    cudaFuncSetAttribute(hgemm_kernel<false, true>,  cudaFuncAttributeMaxDynamicSharedMemorySize, GEMM_SMEM);

    static cudaStream_t s1 = nullptr;
    static cudaEvent_t evFork = nullptr, evJoin = nullptr;
    if (s1 == nullptr) {
        cudaStreamCreateWithFlags(&s1, cudaStreamNonBlocking);
        cudaEventCreateWithFlags(&evFork, cudaEventDisableTiming);
        cudaEventCreateWithFlags(&evJoin, cudaEventDisableTiming);
    }

    auto blocks = [](int n) { return (n + 255) / 256; };

    // #1: zero BN accumulators; fork point
    init_kernel<<<8, 256>>>();
    cudaEventRecord(evFork, 0);
    cudaStreamWaitEvent(s1, evFork, 0);

    // ----- fine path (default stream) -----
    { int n8 = D_L * D_L / 8; cvt_kernel<<<blocks(n8), 256>>>(mid_w1, W1h, n8); }   // #2
    { int n8 = D_L * D_L / 8; cvt_kernel<<<blocks(n8), 256>>>(mid_w2, W2h, n8); }   // #3
    {   // fine_feat -> fp16, split in two launches (keeps ncu -s 5 on GEMM-1)
        int n8 = M_FINE * D_L / 8, h = n8 / 2;
        cvt_kernel<<<blocks(h), 256>>>(fine_feat, A1h, h);                           // #4
        cvt_kernel<<<blocks(n8 - h), 256>>>(fine_feat + (size_t)h * 8,
                                            A1h + (size_t)h * 8, n8 - h);            // #5
    }

    hgemm_kernel<true, false><<<dim3(D_L / 128, M_FINE / 128), 128, GEMM_SMEM>>>(    // #6 <- ncu
        A1h, W1h, mid_b1, nullptr, nullptr, Hfh, nullptr, sf, D_L, D_L);
    bn_finalize_kernel<D_L><<<1, D_L>>>(sf, mid_g1, mid_be1, 1.0f / (float)M_FINE, scf, shf);
    hgemm_kernel<false, true><<<dim3(D_L / 128, M_FINE / 128), 128, GEMM_SMEM>>>(
        Hfh, W2h, mid_b2, scf, shf, nullptr, out + OFF_FINE, nullptr, D_L, D_L);

    fine_epilogue_kernel<<<B_SZ, 512>>>(fine_attn, out + OFF_FINE, out + OFF_TOP);

    // ----- global path (stream s1, overlaps fine path) -----
    { int n8 = D_G * D_L / 8; cvt_kernel<<<blocks(n8), 256, 0, s1>>>(vpt_w1, V1h, n8); }
    { int n8 = D_G * D_G / 8; cvt_kernel<<<blocks(n8), 256, 0, s1>>>(vpt_w2, V2h, n8); }
    { int n8 = B_SZ * D_L / 8; cvt_kernel<<<blocks(n8), 256, 0, s1>>>(image_features, gAh, n8); }

    hgemm_kernel<true, false><<<dim3(D_G / 128, B_SZ / 128), 128, GEMM_SMEM, s1>>>(
        gAh, V1h, vpt_b1, nullptr, nullptr, Hgh, nullptr, sg, D_G, D_L);
    bn_finalize_kernel<D_G><<<1, D_G, 0, s1>>>(sg, vpt_g1, vpt_be1, 1.0f / (float)B_SZ, scg, shg);
    hgemm_kernel<false, true><<<dim3(D_G / 128, B_SZ / 128), 128, GEMM_SMEM, s1>>>(
        Hgh, V2h, vpt_b2, scg, shg, nullptr, G, nullptr, D_G, D_G);
    l2norm_kernel<<<B_SZ, 256, 0, s1>>>(G, logit_scale, out);
    cudaEventRecord(evJoin, s1);

    cudaStreamWaitEvent(0, evJoin, 0);
}